// round 14
// baseline (speedup 1.0000x reference)
#include <cuda_runtime.h>

// QuantumLayer, 2-kernel split + PDL overlap; eval rebuilt for ILP:
//  z_w(x) = sum_{u,v} C[w][u][v]*p01[u]*p23[v], features (1, cos x, sin x).
// Kernel 1 (1 block): shuffle-parallel C builder -> g_C.
// Kernel 2 (PDL secondary): TPB=128, cap 102 regs (5 blocks/SM), persistent
// grid of 740 blocks, grid-stride over 256-element chunks (EPT=2).
// Inner contraction uses 8 independent fma2 chains (even/odd v split) and a
// ~100-reg budget so C loads pipeline ahead of their consuming fma2 groups.

#define TPB    128
#define EPT    2
#define NBLK   740                    // 5 blocks/SM * 148 SMs
#define CHUNK  (TPB * EPT)
#define STRIDE (NBLK * CHUNK)

typedef unsigned long long ull;

__device__ float4 g_C[81];   // [u*9+v] -> (C_w0, C_w1, C_w2, C_w3)

__device__ __forceinline__ ull pk2(float lo, float hi) {
    ull r; asm("mov.b64 %0,{%1,%2};" : "=l"(r) : "f"(lo), "f"(hi)); return r;
}
__device__ __forceinline__ void upk2(ull a, float& lo, float& hi) {
    asm("mov.b64 {%0,%1},%2;" : "=f"(lo), "=f"(hi) : "l"(a));
}
__device__ __forceinline__ ull fma2(ull a, ull b, ull c) {
    ull d; asm("fma.rn.f32x2 %0,%1,%2,%3;" : "=l"(d) : "l"(a), "l"(b), "l"(c)); return d;
}
__device__ __forceinline__ ull mul2(ull a, ull b) {
    ull d; asm("mul.rn.f32x2 %0,%1,%2;" : "=l"(d) : "l"(a), "l"(b)); return d;
}

// ---------------------------------------------------------------------------
// Kernel 1: shuffle-parallel build of C. Thread tid = j*16 + i owns U[i][j].
// ---------------------------------------------------------------------------
__global__ void build_coeff_kernel(const float* __restrict__ weights) {
    cudaTriggerProgrammaticLaunchCompletion();   // let eval's prologue start now
    __shared__ float sUr[16][16], sUi[16][16];
    __shared__ float sM[256 * 4];                // [(j*16+k)*4 + w]
    const int tid = threadIdx.x;
    const int i = tid & 15;

    float vr = (i == (tid >> 4)) ? 1.0f : 0.0f;
    float vi = 0.0f;
#pragma unroll
    for (int l = 0; l < 5; ++l) {
#pragma unroll
        for (int w = 0; w < 4; ++w) {
            const float phi   = __ldg(&weights[(l * 4 + w) * 3 + 0]);
            const float theta = __ldg(&weights[(l * 4 + w) * 3 + 1]);
            const float omega = __ldg(&weights[(l * 4 + w) * 3 + 2]);
            float sp, cp, sm, cm, st, ct;
            __sincosf(0.5f * (phi + omega), &sp, &cp);
            __sincosf(0.5f * (phi - omega), &sm, &cm);
            __sincosf(0.5f * theta, &st, &ct);
            const int m = 8 >> w;
            const float pr = __shfl_xor_sync(0xffffffffu, vr, m);
            const float pi = __shfl_xor_sync(0xffffffffu, vi, m);
            const bool bit = (i & m) != 0;
            const float cAr = cp * ct;
            const float cAi = bit ? sp * ct : -sp * ct;
            const float cBr = bit ? cm * st : -cm * st;
            const float cBi = -sm * st;
            const float nvr = cAr * vr - cAi * vi + cBr * pr - cBi * pi;
            const float nvi = cAr * vi + cAi * vr + cBr * pi + cBi * pr;
            vr = nvr; vi = nvi;
        }
        const int r = (l % 3) + 1;
#pragma unroll
        for (int w = 0; w < 4; ++w) {
            const int mc = 8 >> w;
            const int mt = 8 >> ((w + r) & 3);
            const float pr = __shfl_xor_sync(0xffffffffu, vr, mt);
            const float pi = __shfl_xor_sync(0xffffffffu, vi, mt);
            if (i & mc) { vr = pr; vi = pi; }
        }
    }
    sUr[i][tid >> 4] = vr;
    sUi[i][tid >> 4] = vi;
    __syncthreads();

    {   // M_w[j][k] = sum_i sign_w(i) Re(conj U_ij * U_ik)
        const int j = tid >> 4, k = tid & 15;
        float m0 = 0.f, m1 = 0.f, m2 = 0.f, m3 = 0.f;
#pragma unroll
        for (int ii = 0; ii < 16; ++ii) {
            const float p = sUr[ii][j] * sUr[ii][k] + sUi[ii][j] * sUi[ii][k];
            m0 += (ii & 8) ? -p : p;
            m1 += (ii & 4) ? -p : p;
            m2 += (ii & 2) ? -p : p;
            m3 += (ii & 1) ? -p : p;
        }
        sM[tid * 4 + 0] = m0; sM[tid * 4 + 1] = m1;
        sM[tid * 4 + 2] = m2; sM[tid * 4 + 3] = m3;
    }
    __syncthreads();

    if (tid < 81) {  // project M_w onto (1, cos, sin)^{x4} basis
        const int t0 = tid / 27, t1 = (tid / 9) % 3, t2 = (tid / 3) % 3, t3 = tid % 3;
        const int tt[4] = {t0, t1, t2, t3};
        float a0 = 0.f, a1 = 0.f, a2 = 0.f, a3 = 0.f;
#pragma unroll
        for (int b = 0; b < 16; ++b) {
            int j = 0, k = 0; float sgn = 1.0f;
#pragma unroll
            for (int q = 0; q < 4; ++q) {
                const int o = (b >> q) & 1;
                const int ti = tt[q];
                int jq, kq;
                if (ti == 2) { jq = o; kq = 1 - o; }
                else { jq = o; kq = o; if (ti == 1 && o) sgn = -sgn; }
                j = (j << 1) | jq;
                k = (k << 1) | kq;
            }
            const float* m = &sM[(j * 16 + k) * 4];
            a0 += sgn * m[0]; a1 += sgn * m[1];
            a2 += sgn * m[2]; a3 += sgn * m[3];
        }
        const int u = t0 * 3 + t1, v = t2 * 3 + t3;
        g_C[u * 9 + v] = make_float4(a0 * 0.0625f, a1 * 0.0625f,
                                     a2 * 0.0625f, a3 * 0.0625f);
    }
}

// ---------------------------------------------------------------------------
// Kernel 2 (PDL secondary): persistent, high-ILP contraction (8 fma2 chains).
// ---------------------------------------------------------------------------
__global__ __launch_bounds__(TPB, 5)
void qforward_kernel(const float4* __restrict__ x, float4* __restrict__ out, int B) {
    __shared__ __align__(16) ull shC[162];       // [uv][{w01, w23}]

    const int tid = threadIdx.x;
    int start = blockIdx.x * CHUNK;

    // ---------- prologue: first chunk's features overlap the builder ----------
    ull p23[EPT][9];
    float f0[EPT][3], f1[EPT][3];
    const ull ONE = pk2(1.0f, 1.0f);

    {
        const int i0 = start + tid, i1 = i0 + TPB;
        const float4 xv0 = (i0 < B) ? x[i0] : make_float4(0.f, 0.f, 0.f, 0.f);
        const float4 xv1 = (i1 < B) ? x[i1] : make_float4(0.f, 0.f, 0.f, 0.f);
        const float4 xa[2] = {xv0, xv1};
#pragma unroll
        for (int e = 0; e < EPT; ++e) {
            float c2, s2, c3, s3;
            __sincosf(xa[e].z, &s2, &c2);
            __sincosf(xa[e].w, &s3, &c3);
            const ull c2d = pk2(c2, c2), s2d = pk2(s2, s2);
            const ull c3d = pk2(c3, c3), s3d = pk2(s3, s3);
            p23[e][0] = ONE; p23[e][1] = c3d; p23[e][2] = s3d;
            p23[e][3] = c2d; p23[e][4] = mul2(c2d, c3d); p23[e][5] = mul2(c2d, s3d);
            p23[e][6] = s2d; p23[e][7] = mul2(s2d, c3d); p23[e][8] = mul2(s2d, s3d);
            float c0, s0, c1, s1;
            __sincosf(xa[e].x, &s0, &c0);
            __sincosf(xa[e].y, &s1, &c1);
            f0[e][0] = 1.0f; f0[e][1] = c0; f0[e][2] = s0;
            f1[e][0] = 1.0f; f1[e][1] = c1; f1[e][2] = s1;
        }
    }

    // ---------- wait for builder's g_C, stage to shared ----------
    cudaGridDependencySynchronize();
    if (tid < 81) {
        const float4 c = g_C[tid];
        shC[2 * tid]     = pk2(c.x, c.y);
        shC[2 * tid + 1] = pk2(c.z, c.w);
    }
    __syncthreads();

    const ulonglong2* __restrict__ C2 = reinterpret_cast<const ulonglong2*>(shC);

    // ---------- persistent loop over chunks ----------
    for (;;) {
        // contraction: 8 independent chains (even-v / odd-v per half per elem)
        ull zlo[EPT], zhi[EPT];
#pragma unroll
        for (int e = 0; e < EPT; ++e) { zlo[e] = 0ull; zhi[e] = 0ull; }

#pragma unroll
        for (int u = 0; u < 9; ++u) {
            ull aAlo[EPT] = {0ull, 0ull}, aAhi[EPT] = {0ull, 0ull};
            ull aBlo[EPT] = {0ull, 0ull}, aBhi[EPT] = {0ull, 0ull};
#pragma unroll
            for (int v = 0; v < 8; v += 2) {
                const ulonglong2 cA = C2[u * 9 + v];
                const ulonglong2 cB = C2[u * 9 + v + 1];
#pragma unroll
                for (int e = 0; e < EPT; ++e) {
                    aAlo[e] = fma2(cA.x, p23[e][v],     aAlo[e]);
                    aAhi[e] = fma2(cA.y, p23[e][v],     aAhi[e]);
                    aBlo[e] = fma2(cB.x, p23[e][v + 1], aBlo[e]);
                    aBhi[e] = fma2(cB.y, p23[e][v + 1], aBhi[e]);
                }
            }
            {   // v = 8 tail -> A chains
                const ulonglong2 cT = C2[u * 9 + 8];
#pragma unroll
                for (int e = 0; e < EPT; ++e) {
                    aAlo[e] = fma2(cT.x, p23[e][8], aAlo[e]);
                    aAhi[e] = fma2(cT.y, p23[e][8], aAhi[e]);
                }
            }
#pragma unroll
            for (int e = 0; e < EPT; ++e) {
                const float puf = f0[e][u / 3] * f1[e][u % 3];  // static; 1.0 folds
                const ull pu = pk2(puf, puf);
                zlo[e] = fma2(aAlo[e], pu, zlo[e]);
                zlo[e] = fma2(aBlo[e], pu, zlo[e]);
                zhi[e] = fma2(aAhi[e], pu, zhi[e]);
                zhi[e] = fma2(aBhi[e], pu, zhi[e]);
            }
        }

        // store
#pragma unroll
        for (int e = 0; e < EPT; ++e) {
            const int idx = start + tid + e * TPB;
            if (idx < B) {
                float z0, z1, z2, z3;
                upk2(zlo[e], z0, z1); upk2(zhi[e], z2, z3);
                out[idx] = make_float4(z0, z1, z2, z3);
            }
        }

        // next chunk
        start += STRIDE;
        if (start >= B) break;
        {
            const int i0 = start + tid, i1 = i0 + TPB;
            const float4 xv0 = (i0 < B) ? x[i0] : make_float4(0.f, 0.f, 0.f, 0.f);
            const float4 xv1 = (i1 < B) ? x[i1] : make_float4(0.f, 0.f, 0.f, 0.f);
            const float4 xa[2] = {xv0, xv1};
#pragma unroll
            for (int e = 0; e < EPT; ++e) {
                float c2, s2, c3, s3;
                __sincosf(xa[e].z, &s2, &c2);
                __sincosf(xa[e].w, &s3, &c3);
                const ull c2d = pk2(c2, c2), s2d = pk2(s2, s2);
                const ull c3d = pk2(c3, c3), s3d = pk2(s3, s3);
                p23[e][0] = ONE; p23[e][1] = c3d; p23[e][2] = s3d;
                p23[e][3] = c2d; p23[e][4] = mul2(c2d, c3d); p23[e][5] = mul2(c2d, s3d);
                p23[e][6] = s2d; p23[e][7] = mul2(s2d, c3d); p23[e][8] = mul2(s2d, s3d);
                float c0, s0, c1, s1;
                __sincosf(xa[e].x, &s0, &c0);
                __sincosf(xa[e].y, &s1, &c1);
                f0[e][0] = 1.0f; f0[e][1] = c0; f0[e][2] = s0;
                f1[e][0] = 1.0f; f1[e][1] = c1; f1[e][2] = s1;
            }
        }
    }
}

// ---------------------------------------------------------------------------
extern "C" void kernel_launch(void* const* d_in, const int* in_sizes, int n_in,
                              void* d_out, int out_size) {
    int bx = 0, bw = 1;
    if (n_in >= 2 && in_sizes[0] == 60) { bx = 1; bw = 0; }
    const float* x   = (const float*)d_in[bx];
    const float* wts = (const float*)d_in[bw];
    const int B = in_sizes[bx] / 4;

    build_coeff_kernel<<<1, 256>>>(wts);

    int grid = (B + CHUNK - 1) / CHUNK;
    if (grid > NBLK) grid = NBLK;
    cudaLaunchConfig_t cfg = {};
    cfg.gridDim  = dim3((unsigned)grid, 1, 1);
    cfg.blockDim = dim3(TPB, 1, 1);
    cudaLaunchAttribute attrs[1];
    attrs[0].id = cudaLaunchAttributeProgrammaticStreamSerialization;
    attrs[0].val.programmaticStreamSerializationAllowed = 1;
    cfg.attrs = attrs;
    cfg.numAttrs = 1;
    cudaLaunchKernelEx(&cfg, qforward_kernel, (const float4*)x, (float4*)d_out, B);
}

// round 15
// speedup vs baseline: 4.0613x; 4.0613x over previous
#include <cuda_runtime.h>

// QuantumLayer, 2-kernel split + PDL overlap; straight-line EPT=1 eval:
//  z_w(x) = sum_{u,v} C[w][u][v]*p01[u]*p23[v], features (1, cos x, sin x).
// Kernel 1 (1 block): shuffle-parallel C builder -> g_C.
// Kernel 2 (PDL secondary): one element per thread, 2048 blocks of 128.
// Live set ~48 regs under a 64-reg cap (8 blocks/SM = 32 warps/SM) leaves
// true headroom for C-load pipelining -- no spills, no loop-carried state.

#define TPB 128

typedef unsigned long long ull;

__device__ float4 g_C[81];   // [u*9+v] -> (C_w0, C_w1, C_w2, C_w3)

__device__ __forceinline__ ull pk2(float lo, float hi) {
    ull r; asm("mov.b64 %0,{%1,%2};" : "=l"(r) : "f"(lo), "f"(hi)); return r;
}
__device__ __forceinline__ void upk2(ull a, float& lo, float& hi) {
    asm("mov.b64 {%0,%1},%2;" : "=f"(lo), "=f"(hi) : "l"(a));
}
__device__ __forceinline__ ull fma2(ull a, ull b, ull c) {
    ull d; asm("fma.rn.f32x2 %0,%1,%2,%3;" : "=l"(d) : "l"(a), "l"(b), "l"(c)); return d;
}
__device__ __forceinline__ ull mul2(ull a, ull b) {
    ull d; asm("mul.rn.f32x2 %0,%1,%2;" : "=l"(d) : "l"(a), "l"(b)); return d;
}

// ---------------------------------------------------------------------------
// Kernel 1: shuffle-parallel build of C. Thread tid = j*16 + i owns U[i][j].
// ---------------------------------------------------------------------------
__global__ void build_coeff_kernel(const float* __restrict__ weights) {
    cudaTriggerProgrammaticLaunchCompletion();   // let eval's prologue start now
    __shared__ float sUr[16][16], sUi[16][16];
    __shared__ float sM[256 * 4];                // [(j*16+k)*4 + w]
    const int tid = threadIdx.x;
    const int i = tid & 15;

    float vr = (i == (tid >> 4)) ? 1.0f : 0.0f;
    float vi = 0.0f;
#pragma unroll
    for (int l = 0; l < 5; ++l) {
#pragma unroll
        for (int w = 0; w < 4; ++w) {
            const float phi   = __ldg(&weights[(l * 4 + w) * 3 + 0]);
            const float theta = __ldg(&weights[(l * 4 + w) * 3 + 1]);
            const float omega = __ldg(&weights[(l * 4 + w) * 3 + 2]);
            float sp, cp, sm, cm, st, ct;
            __sincosf(0.5f * (phi + omega), &sp, &cp);
            __sincosf(0.5f * (phi - omega), &sm, &cm);
            __sincosf(0.5f * theta, &st, &ct);
            const int m = 8 >> w;
            const float pr = __shfl_xor_sync(0xffffffffu, vr, m);
            const float pi = __shfl_xor_sync(0xffffffffu, vi, m);
            const bool bit = (i & m) != 0;
            const float cAr = cp * ct;
            const float cAi = bit ? sp * ct : -sp * ct;
            const float cBr = bit ? cm * st : -cm * st;
            const float cBi = -sm * st;
            const float nvr = cAr * vr - cAi * vi + cBr * pr - cBi * pi;
            const float nvi = cAr * vi + cAi * vr + cBr * pi + cBi * pr;
            vr = nvr; vi = nvi;
        }
        const int r = (l % 3) + 1;
#pragma unroll
        for (int w = 0; w < 4; ++w) {
            const int mc = 8 >> w;
            const int mt = 8 >> ((w + r) & 3);
            const float pr = __shfl_xor_sync(0xffffffffu, vr, mt);
            const float pi = __shfl_xor_sync(0xffffffffu, vi, mt);
            if (i & mc) { vr = pr; vi = pi; }
        }
    }
    sUr[i][tid >> 4] = vr;
    sUi[i][tid >> 4] = vi;
    __syncthreads();

    {   // M_w[j][k] = sum_i sign_w(i) Re(conj U_ij * U_ik)
        const int j = tid >> 4, k = tid & 15;
        float m0 = 0.f, m1 = 0.f, m2 = 0.f, m3 = 0.f;
#pragma unroll
        for (int ii = 0; ii < 16; ++ii) {
            const float p = sUr[ii][j] * sUr[ii][k] + sUi[ii][j] * sUi[ii][k];
            m0 += (ii & 8) ? -p : p;
            m1 += (ii & 4) ? -p : p;
            m2 += (ii & 2) ? -p : p;
            m3 += (ii & 1) ? -p : p;
        }
        sM[tid * 4 + 0] = m0; sM[tid * 4 + 1] = m1;
        sM[tid * 4 + 2] = m2; sM[tid * 4 + 3] = m3;
    }
    __syncthreads();

    if (tid < 81) {  // project M_w onto (1, cos, sin)^{x4} basis
        const int t0 = tid / 27, t1 = (tid / 9) % 3, t2 = (tid / 3) % 3, t3 = tid % 3;
        const int tt[4] = {t0, t1, t2, t3};
        float a0 = 0.f, a1 = 0.f, a2 = 0.f, a3 = 0.f;
#pragma unroll
        for (int b = 0; b < 16; ++b) {
            int j = 0, k = 0; float sgn = 1.0f;
#pragma unroll
            for (int q = 0; q < 4; ++q) {
                const int o = (b >> q) & 1;
                const int ti = tt[q];
                int jq, kq;
                if (ti == 2) { jq = o; kq = 1 - o; }
                else { jq = o; kq = o; if (ti == 1 && o) sgn = -sgn; }
                j = (j << 1) | jq;
                k = (k << 1) | kq;
            }
            const float* m = &sM[(j * 16 + k) * 4];
            a0 += sgn * m[0]; a1 += sgn * m[1];
            a2 += sgn * m[2]; a3 += sgn * m[3];
        }
        const int u = t0 * 3 + t1, v = t2 * 3 + t3;
        g_C[u * 9 + v] = make_float4(a0 * 0.0625f, a1 * 0.0625f,
                                     a2 * 0.0625f, a3 * 0.0625f);
    }
}

// ---------------------------------------------------------------------------
// Kernel 2 (PDL secondary): straight-line, one element per thread.
// ---------------------------------------------------------------------------
__global__ __launch_bounds__(TPB, 8)
void qforward_kernel(const float4* __restrict__ x, float4* __restrict__ out, int B) {
    __shared__ __align__(16) ull shC[162];       // [uv][{w01, w23}]

    const int idx = blockIdx.x * TPB + threadIdx.x;
    const bool valid = (idx < B);

    // ---------- prologue: independent of C, overlaps the builder ----------
    const float4 xv = valid ? x[idx] : make_float4(0.f, 0.f, 0.f, 0.f);
    const ull ONE = pk2(1.0f, 1.0f);

    float c2, s2, c3, s3;
    __sincosf(xv.z, &s2, &c2);
    __sincosf(xv.w, &s3, &c3);
    ull p23[9];
    {
        const ull c2d = pk2(c2, c2), s2d = pk2(s2, s2);
        const ull c3d = pk2(c3, c3), s3d = pk2(s3, s3);
        p23[0] = ONE; p23[1] = c3d; p23[2] = s3d;
        p23[3] = c2d; p23[4] = mul2(c2d, c3d); p23[5] = mul2(c2d, s3d);
        p23[6] = s2d; p23[7] = mul2(s2d, c3d); p23[8] = mul2(s2d, s3d);
    }
    float c0, s0, c1, s1;
    __sincosf(xv.x, &s0, &c0);
    __sincosf(xv.y, &s1, &c1);
    const float f0a[3] = {1.0f, c0, s0};
    const float f1a[3] = {1.0f, c1, s1};

    // ---------- wait for builder's g_C, stage to shared ----------
    cudaGridDependencySynchronize();
    if (threadIdx.x < 81) {
        const float4 c = g_C[threadIdx.x];
        shC[2 * threadIdx.x]     = pk2(c.x, c.y);
        shC[2 * threadIdx.x + 1] = pk2(c.z, c.w);
    }
    __syncthreads();

    // ---------- contraction: z = sum_u p01[u] * (sum_v C[u][v] * p23[v]) ----
    const ulonglong2* __restrict__ C2 = reinterpret_cast<const ulonglong2*>(shC);
    ull zlo, zhi;
    {   // u = 0: p01 factor is 1 -> z initialized by inner sums directly
        ull alo = 0ull, ahi = 0ull;
#pragma unroll
        for (int v = 0; v < 9; ++v) {
            const ulonglong2 c = C2[v];
            alo = fma2(c.x, p23[v], alo);
            ahi = fma2(c.y, p23[v], ahi);
        }
        zlo = alo; zhi = ahi;
    }
#pragma unroll
    for (int u = 1; u < 9; ++u) {
        ull alo = 0ull, ahi = 0ull;
#pragma unroll
        for (int v = 0; v < 9; ++v) {
            const ulonglong2 c = C2[u * 9 + v];   // LDS.128, warp-uniform bcast
            alo = fma2(c.x, p23[v], alo);
            ahi = fma2(c.y, p23[v], ahi);
        }
        const float puf = f0a[u / 3] * f1a[u % 3];  // static idx; 1.0 folds away
        const ull pu = pk2(puf, puf);
        zlo = fma2(alo, pu, zlo);
        zhi = fma2(ahi, pu, zhi);
    }

    if (valid) {
        float z0, z1, z2, z3;
        upk2(zlo, z0, z1); upk2(zhi, z2, z3);
        out[idx] = make_float4(z0, z1, z2, z3);
    }
}

// ---------------------------------------------------------------------------
extern "C" void kernel_launch(void* const* d_in, const int* in_sizes, int n_in,
                              void* d_out, int out_size) {
    int bx = 0, bw = 1;
    if (n_in >= 2 && in_sizes[0] == 60) { bx = 1; bw = 0; }
    const float* x   = (const float*)d_in[bx];
    const float* wts = (const float*)d_in[bw];
    const int B = in_sizes[bx] / 4;

    build_coeff_kernel<<<1, 256>>>(wts);

    const int grid = (B + TPB - 1) / TPB;
    cudaLaunchConfig_t cfg = {};
    cfg.gridDim  = dim3((unsigned)grid, 1, 1);
    cfg.blockDim = dim3(TPB, 1, 1);
    cudaLaunchAttribute attrs[1];
    attrs[0].id = cudaLaunchAttributeProgrammaticStreamSerialization;
    attrs[0].val.programmaticStreamSerializationAllowed = 1;
    cfg.attrs = attrs;
    cfg.numAttrs = 1;
    cudaLaunchKernelEx(&cfg, qforward_kernel, (const float4*)x, (float4*)d_out, B);
}

// round 16
// speedup vs baseline: 4.1336x; 1.0178x over previous
#include <cuda_runtime.h>

// QuantumLayer, 2-kernel split + PDL; latency-parallel builder + R13 eval.
//  z_w(x) = sum_{u,v} C[w][u][v]*p01[u]*p23[v], features (1, cos x, sin x).
// Builder (1 block, 512 thr): 5 layer unitaries element-parallel (CNOT perm
// folded into row index), 3-level matmul tree, then M_w and C projection.
// Eval (PDL secondary): R13's measured-best EPT=2 straight-line contraction.

#define TPB 128
#define EPT 2

typedef unsigned long long ull;

__device__ float4 g_C[81];   // [u*9+v] -> (C_w0, C_w1, C_w2, C_w3)

__device__ __forceinline__ ull pk2(float lo, float hi) {
    ull r; asm("mov.b64 %0,{%1,%2};" : "=l"(r) : "f"(lo), "f"(hi)); return r;
}
__device__ __forceinline__ void upk2(ull a, float& lo, float& hi) {
    asm("mov.b64 {%0,%1},%2;" : "=f"(lo), "=f"(hi) : "l"(a));
}
__device__ __forceinline__ ull fma2(ull a, ull b, ull c) {
    ull d; asm("fma.rn.f32x2 %0,%1,%2,%3;" : "=l"(d) : "l"(a), "l"(b), "l"(c)); return d;
}
__device__ __forceinline__ ull mul2(ull a, ull b) {
    ull d; asm("mul.rn.f32x2 %0,%1,%2;" : "=l"(d) : "l"(a), "l"(b)); return d;
}

// ---------------------------------------------------------------------------
// Kernel 1: latency-parallel C builder.
//   U_layer[i][j] = R_tensor[perm_l(i)][j];  U = U4*U3*U2*U1*U0 (tree);
//   M_w[j][k] = sum_i sign_w(i) Re(conj U_ij U_ik);  C = basis projection.
// ---------------------------------------------------------------------------
__global__ void build_coeff_kernel(const float* __restrict__ weights) {
    cudaTriggerProgrammaticLaunchCompletion();   // eval's prologue may start
    __shared__ float2 sL[5][256];                // layer unitaries [l][i*16+j]
    __shared__ float2 sP1[256], sP2[256], sQ[256], sF[256];
    __shared__ float  sM[256 * 4];               // [(j*16+k)*4 + w]
    const int tid = threadIdx.x;
    const int e   = tid & 255;
    const int ei  = e >> 4, ej = e & 15;         // row, col of owned element

    // ---- Stage 1: all layer unitaries, element-parallel (no serial chain) --
    for (int l = (tid >> 8); l < 5; l += 2) {
        const int r = (l % 3) + 1;
        // row permutation from the 4 CNOTs: U_layer[i][j] = R[c0(c1(c2(c3(i))))][j]
        int m = ei;
#pragma unroll
        for (int w = 3; w >= 0; --w) {
            const int mc = 8 >> w;
            const int mt = 8 >> ((w + r) & 3);
            if (m & mc) m ^= mt;
        }
        // product over wires of R_q[m_q][j_q]
        float pr = 1.0f, pi = 0.0f;
#pragma unroll
        for (int q = 0; q < 4; ++q) {
            const float phi   = __ldg(&weights[(l * 4 + q) * 3 + 0]);
            const float theta = __ldg(&weights[(l * 4 + q) * 3 + 1]);
            const float omega = __ldg(&weights[(l * 4 + q) * 3 + 2]);
            float sp, cp, sm, cm, st, ct;
            __sincosf(0.5f * (phi + omega), &sp, &cp);
            __sincosf(0.5f * (phi - omega), &sm, &cm);
            __sincosf(0.5f * theta, &st, &ct);
            const int mb = (m  >> (3 - q)) & 1;
            const int jb = (ej >> (3 - q)) & 1;
            float er, ei2;
            if (mb == jb)     { er = cp * ct; ei2 = mb ? sp * ct : -sp * ct; }
            else if (mb == 0) { er = -cm * st; ei2 = -sm * st; }   // R[0][1]
            else              { er =  cm * st; ei2 = -sm * st; }   // R[1][0]
            const float nr = pr * er - pi * ei2;
            const float ni = pr * ei2 + pi * er;
            pr = nr; pi = ni;
        }
        sL[l][e] = make_float2(pr, pi);
    }
    __syncthreads();

    // ---- Stage 2: matmul tree, level 1: P1 = U4*U3 (thr 0-255), P2 = U2*U1 --
    {
        const float2* A  = (tid < 256) ? sL[4] : sL[2];
        const float2* Bm = (tid < 256) ? sL[3] : sL[1];
        float2* D        = (tid < 256) ? sP1   : sP2;
        float ar = 0.f, ai = 0.f;
#pragma unroll
        for (int k = 0; k < 16; ++k) {
            const float2 a = A[ei * 16 + k];
            const float2 b = Bm[k * 16 + ej];
            ar += a.x * b.x - a.y * b.y;
            ai += a.x * b.y + a.y * b.x;
        }
        D[e] = make_float2(ar, ai);
    }
    __syncthreads();

    // ---- level 2: Q = P1*P2 ----
    if (tid < 256) {
        float ar = 0.f, ai = 0.f;
#pragma unroll
        for (int k = 0; k < 16; ++k) {
            const float2 a = sP1[ei * 16 + k];
            const float2 b = sP2[k * 16 + ej];
            ar += a.x * b.x - a.y * b.y;
            ai += a.x * b.y + a.y * b.x;
        }
        sQ[e] = make_float2(ar, ai);
    }
    __syncthreads();

    // ---- level 3: F = Q*U0  (full circuit unitary) ----
    if (tid < 256) {
        float ar = 0.f, ai = 0.f;
#pragma unroll
        for (int k = 0; k < 16; ++k) {
            const float2 a = sQ[ei * 16 + k];
            const float2 b = sL[0][k * 16 + ej];
            ar += a.x * b.x - a.y * b.y;
            ai += a.x * b.y + a.y * b.x;
        }
        sF[e] = make_float2(ar, ai);
    }
    __syncthreads();

    // ---- Stage 3: M_w[j][k] = sum_i sign_w(i) Re(conj U_ij * U_ik) ----
    if (tid < 256) {
        const int j = tid >> 4, k = tid & 15;
        float m0 = 0.f, m1 = 0.f, m2 = 0.f, m3 = 0.f;
#pragma unroll
        for (int ii = 0; ii < 16; ++ii) {
            const float2 uj = sF[ii * 16 + j];
            const float2 uk = sF[ii * 16 + k];
            const float p = uj.x * uk.x + uj.y * uk.y;
            m0 += (ii & 8) ? -p : p;
            m1 += (ii & 4) ? -p : p;
            m2 += (ii & 2) ? -p : p;
            m3 += (ii & 1) ? -p : p;
        }
        sM[tid * 4 + 0] = m0; sM[tid * 4 + 1] = m1;
        sM[tid * 4 + 2] = m2; sM[tid * 4 + 3] = m3;
    }
    __syncthreads();

    // ---- Stage 4: project M_w onto (1, cos, sin)^{x4} basis -> g_C ----
    if (tid < 81) {
        const int t0 = tid / 27, t1 = (tid / 9) % 3, t2 = (tid / 3) % 3, t3 = tid % 3;
        const int tt[4] = {t0, t1, t2, t3};
        float a0 = 0.f, a1 = 0.f, a2 = 0.f, a3 = 0.f;
#pragma unroll
        for (int b = 0; b < 16; ++b) {
            int j = 0, k = 0; float sgn = 1.0f;
#pragma unroll
            for (int q = 0; q < 4; ++q) {
                const int o = (b >> q) & 1;
                const int ti = tt[q];
                int jq, kq;
                if (ti == 2) { jq = o; kq = 1 - o; }
                else { jq = o; kq = o; if (ti == 1 && o) sgn = -sgn; }
                j = (j << 1) | jq;
                k = (k << 1) | kq;
            }
            const float* m = &sM[(j * 16 + k) * 4];
            a0 += sgn * m[0]; a1 += sgn * m[1];
            a2 += sgn * m[2]; a3 += sgn * m[3];
        }
        const int u = t0 * 3 + t1, v = t2 * 3 + t3;
        g_C[u * 9 + v] = make_float4(a0 * 0.0625f, a1 * 0.0625f,
                                     a2 * 0.0625f, a3 * 0.0625f);
    }
}

// ---------------------------------------------------------------------------
// Kernel 2 (PDL secondary): R13's straight-line EPT=2 eval (8.83us measured).
// ---------------------------------------------------------------------------
__global__ __launch_bounds__(TPB, 7)
void qforward_kernel(const float4* __restrict__ x, float4* __restrict__ out, int B) {
    __shared__ __align__(16) ull shC[162];       // [uv][{w01, w23}]

    const int base = blockIdx.x * (TPB * EPT) + threadIdx.x;

    // ---------- prologue: independent of C, overlaps the builder ----------
    ull p23[EPT][9];
    float f0[EPT][3], f1[EPT][3];
    bool valid[EPT];
    const ull ONE = pk2(1.0f, 1.0f);
#pragma unroll
    for (int e = 0; e < EPT; ++e) {
        const int idx = base + e * TPB;
        valid[e] = (idx < B);
        const float4 xv = valid[e] ? x[idx] : make_float4(0.f, 0.f, 0.f, 0.f);
        float c2, s2, c3, s3;
        __sincosf(xv.z, &s2, &c2);
        __sincosf(xv.w, &s3, &c3);
        const ull c2d = pk2(c2, c2), s2d = pk2(s2, s2);
        const ull c3d = pk2(c3, c3), s3d = pk2(s3, s3);
        p23[e][0] = ONE; p23[e][1] = c3d; p23[e][2] = s3d;
        p23[e][3] = c2d; p23[e][4] = mul2(c2d, c3d); p23[e][5] = mul2(c2d, s3d);
        p23[e][6] = s2d; p23[e][7] = mul2(s2d, c3d); p23[e][8] = mul2(s2d, s3d);
        float c0, s0, c1, s1;
        __sincosf(xv.x, &s0, &c0);
        __sincosf(xv.y, &s1, &c1);
        f0[e][0] = 1.0f; f0[e][1] = c0; f0[e][2] = s0;
        f1[e][0] = 1.0f; f1[e][1] = c1; f1[e][2] = s1;
    }

    // ---------- wait for builder's g_C, stage to shared ----------
    cudaGridDependencySynchronize();
    if (threadIdx.x < 81) {
        const float4 c = g_C[threadIdx.x];
        shC[2 * threadIdx.x]     = pk2(c.x, c.y);
        shC[2 * threadIdx.x + 1] = pk2(c.z, c.w);
    }
    __syncthreads();

    // ---------- contraction ----------
    const ulonglong2* __restrict__ C2 = reinterpret_cast<const ulonglong2*>(shC);
    ull zlo[EPT], zhi[EPT];

    {   // u = 0: p01 factor is 1 -> z initialized by inner sums directly
        ull alo[EPT] = {0ull, 0ull}, ahi[EPT] = {0ull, 0ull};
#pragma unroll
        for (int v = 0; v < 9; ++v) {
            const ulonglong2 c = C2[v];
#pragma unroll
            for (int e = 0; e < EPT; ++e) {
                alo[e] = fma2(c.x, p23[e][v], alo[e]);
                ahi[e] = fma2(c.y, p23[e][v], ahi[e]);
            }
        }
#pragma unroll
        for (int e = 0; e < EPT; ++e) { zlo[e] = alo[e]; zhi[e] = ahi[e]; }
    }
#pragma unroll
    for (int u = 1; u < 9; ++u) {
        ull alo[EPT] = {0ull, 0ull}, ahi[EPT] = {0ull, 0ull};
#pragma unroll
        for (int v = 0; v < 9; ++v) {
            const ulonglong2 c = C2[u * 9 + v];   // LDS.128, warp-uniform bcast
#pragma unroll
            for (int e = 0; e < EPT; ++e) {
                alo[e] = fma2(c.x, p23[e][v], alo[e]);
                ahi[e] = fma2(c.y, p23[e][v], ahi[e]);
            }
        }
#pragma unroll
        for (int e = 0; e < EPT; ++e) {
            const float puf = f0[e][u / 3] * f1[e][u % 3];  // static idx; 1.0 folds
            const ull pu = pk2(puf, puf);
            zlo[e] = fma2(alo[e], pu, zlo[e]);
            zhi[e] = fma2(ahi[e], pu, zhi[e]);
        }
    }

#pragma unroll
    for (int e = 0; e < EPT; ++e) {
        const int idx = base + e * TPB;
        if (valid[e]) {
            float z0, z1, z2, z3;
            upk2(zlo[e], z0, z1);
            upk2(zhi[e], z2, z3);
            out[idx] = make_float4(z0, z1, z2, z3);
        }
    }
}

// ---------------------------------------------------------------------------
extern "C" void kernel_launch(void* const* d_in, const int* in_sizes, int n_in,
                              void* d_out, int out_size) {
    int bx = 0, bw = 1;
    if (n_in >= 2 && in_sizes[0] == 60) { bx = 1; bw = 0; }
    const float* x   = (const float*)d_in[bx];
    const float* wts = (const float*)d_in[bw];
    const int B = in_sizes[bx] / 4;

    build_coeff_kernel<<<1, 512>>>(wts);

    const int grid = (B + TPB * EPT - 1) / (TPB * EPT);
    cudaLaunchConfig_t cfg = {};
    cfg.gridDim  = dim3((unsigned)grid, 1, 1);
    cfg.blockDim = dim3(TPB, 1, 1);
    cudaLaunchAttribute attrs[1];
    attrs[0].id = cudaLaunchAttributeProgrammaticStreamSerialization;
    attrs[0].val.programmaticStreamSerializationAllowed = 1;
    cfg.attrs = attrs;
    cfg.numAttrs = 1;
    cudaLaunchKernelEx(&cfg, qforward_kernel, (const float4*)x, (float4*)d_out, B);
}